// round 3
// baseline (speedup 1.0000x reference)
#include <cuda_runtime.h>
#include <cuda_bf16.h>

#define BATCH 32
#define SEQ   2048
#define EDIM  128
#define HVOC  500000
#define HBASE 257
#define NPOS  (BATCH * SEQ)
#define PPW   8                      // positions per warp
#define NWARPS (NPOS / PPW)          // 8192

// Compute the 6 n-gram hash indices for position s (shared 7-step chain).
__device__ __forceinline__ void compute_idx(const int* __restrict__ trow,
                                            int s, int idx[6]) {
    const int x0 = __ldg(&trow[s]);
    int h = x0;
#pragma unroll
    for (int j = 1; j <= 7; j++) {
        const int prev = (s - j >= 0) ? __ldg(&trow[s - j]) : 0;
        h = (h * HBASE + prev) % HVOC;
        if (j >= 2) idx[j - 2] = (s >= j) ? h : x0;   // n = j+1
    }
}

// Issue the 6 independent 512B gathers (one float4 per lane) into v[].
__device__ __forceinline__ void issue_gathers(const float* __restrict__ tables,
                                              const int idx[6], int lane,
                                              float4 v[6]) {
#pragma unroll
    for (int k = 0; k < 6; k++) {
        const float4* __restrict__ row = reinterpret_cast<const float4*>(
            tables + ((long)k * HVOC + (long)idx[k]) * EDIM);
        v[k] = __ldcg(&row[lane]);
    }
}

// Depth-2 software pipeline over PPW consecutive positions per warp:
// gathers for position i are in flight while the hash chain + gather issue
// for position i+1 executes; consumption of i happens after.
__global__ __launch_bounds__(256) void ngram_embed_kernel(
    const int* __restrict__ tokens,     // (B, S) int32
    const float* __restrict__ tables,   // (6, V, D) fp32
    float* __restrict__ out)            // (B, S, D) fp32
{
    const int gwarp = (blockIdx.x * blockDim.x + threadIdx.x) >> 5;
    const int lane  = threadIdx.x & 31;
    if (gwarp >= NWARPS) return;

    const int pos0  = gwarp * PPW;           // chunk start (same token row: SEQ%PPW==0)
    const int b     = pos0 >> 11;            // / SEQ
    const int sbase = pos0 & (SEQ - 1);      // % SEQ

    const int* __restrict__ trow = tokens + (long)b * SEQ;
    float4* __restrict__ orow = reinterpret_cast<float4*>(out + (long)pos0 * EDIM);

    const float inv6 = 1.0f / 6.0f;

    int    idx[6];
    float4 vA[6], vB[6];

    // Prologue: position 0
    compute_idx(trow, sbase, idx);
    issue_gathers(tables, idx, lane, vA);

#pragma unroll
    for (int i = 0; i < PPW; i++) {
        // Overlap: hash + issue for position i+1 while vA loads are in flight.
        if (i + 1 < PPW) {
            compute_idx(trow, sbase + i + 1, idx);
            issue_gathers(tables, idx, lane, vB);
        }

        // Consume position i (first use of vA -> scoreboard wait here).
        float4 acc;
        acc.x = vA[0].x + vA[1].x + vA[2].x + vA[3].x + vA[4].x + vA[5].x;
        acc.y = vA[0].y + vA[1].y + vA[2].y + vA[3].y + vA[4].y + vA[5].y;
        acc.z = vA[0].z + vA[1].z + vA[2].z + vA[3].z + vA[4].z + vA[5].z;
        acc.w = vA[0].w + vA[1].w + vA[2].w + vA[3].w + vA[4].w + vA[5].w;
        acc.x *= inv6; acc.y *= inv6; acc.z *= inv6; acc.w *= inv6;
        __stcs(&orow[(long)i * (EDIM / 4) + lane], acc);

        // Rotate pipeline registers (renamed away by full unroll).
        if (i + 1 < PPW) {
#pragma unroll
            for (int k = 0; k < 6; k++) vA[k] = vB[k];
        }
    }
}

extern "C" void kernel_launch(void* const* d_in, const int* in_sizes, int n_in,
                              void* d_out, int out_size) {
    const int*   tokens = (const int*)d_in[0];
    const float* tables = (const float*)d_in[1];
    float*       out    = (float*)d_out;

    const int threads = 256;                         // 8 warps/block
    const int blocks  = NWARPS / (threads / 32);     // 1024
    ngram_embed_kernel<<<blocks, threads>>>(tokens, tables, out);
}

// round 4
// speedup vs baseline: 1.1403x; 1.1403x over previous
#include <cuda_runtime.h>
#include <cuda_bf16.h>

#define BATCH 32
#define SEQ   2048
#define EDIM  128
#define HVOC  500000
#define HBASE 257
#define NPOS  (BATCH * SEQ)
#define PPW   4                       // positions per warp
#define NWARPS (NPOS / PPW)           // 16384

// 6 n-gram hash indices for position s (7-step shared rolling chain).
__device__ __forceinline__ void compute_idx(const int* __restrict__ trow,
                                            int s, int idx[6]) {
    const int x0 = __ldg(&trow[s]);
    int h = x0;
#pragma unroll
    for (int j = 1; j <= 7; j++) {
        const int prev = (s - j >= 0) ? __ldg(&trow[s - j]) : 0;
        h = (h * HBASE + prev) % HVOC;
        if (j >= 2) idx[j - 2] = (s >= j) ? h : x0;   // n = j+1
    }
}

__device__ __forceinline__ void issue_gathers(const float* __restrict__ tables,
                                              const int idx[6], int lane,
                                              float4 v[6]) {
#pragma unroll
    for (int k = 0; k < 6; k++) {
        const float4* __restrict__ row = reinterpret_cast<const float4*>(
            tables + ((long)k * HVOC + (long)idx[k]) * EDIM);
        v[k] = __ldcg(&row[lane]);
    }
}

__device__ __forceinline__ void consume(const float4 v[6], float4* __restrict__ dst,
                                        int lane) {
    const float inv6 = 1.0f / 6.0f;
    float4 acc;
    acc.x = (v[0].x + v[1].x) + (v[2].x + v[3].x) + (v[4].x + v[5].x);
    acc.y = (v[0].y + v[1].y) + (v[2].y + v[3].y) + (v[4].y + v[5].y);
    acc.z = (v[0].z + v[1].z) + (v[2].z + v[3].z) + (v[4].z + v[5].z);
    acc.w = (v[0].w + v[1].w) + (v[2].w + v[3].w) + (v[4].w + v[5].w);
    acc.x *= inv6; acc.y *= inv6; acc.z *= inv6; acc.w *= inv6;
    __stcs(&dst[lane], acc);
}

// Depth-2 software pipeline over PPW positions, NO buffer copies:
// two iterations unrolled with alternating vA/vB roles. At every consumption
// point the next position's 6 gathers are already issued.
__global__ __launch_bounds__(256) void ngram_embed_kernel(
    const int* __restrict__ tokens,     // (B, S) int32
    const float* __restrict__ tables,   // (6, V, D) fp32
    float* __restrict__ out)            // (B, S, D) fp32
{
    const int gwarp = (blockIdx.x * blockDim.x + threadIdx.x) >> 5;
    const int lane  = threadIdx.x & 31;
    if (gwarp >= NWARPS) return;

    const int pos0  = gwarp * PPW;           // SEQ % PPW == 0 -> same token row
    const int b     = pos0 >> 11;
    const int sbase = pos0 & (SEQ - 1);

    const int* __restrict__ trow = tokens + (long)b * SEQ;
    float4* __restrict__ orow = reinterpret_cast<float4*>(out + (long)pos0 * EDIM);

    int    idx[6];
    float4 vA[6], vB[6];

    // Prologue: position 0 in flight.
    compute_idx(trow, sbase, idx);
    issue_gathers(tables, idx, lane, vA);

#pragma unroll
    for (int i = 0; i < PPW; i += 2) {
        // position i+1 into vB (overlaps vA's latency)
        if (i + 1 < PPW) {
            compute_idx(trow, sbase + i + 1, idx);
            issue_gathers(tables, idx, lane, vB);
        }
        // consume position i (waits only on vA)
        consume(vA, orow + (long)i * (EDIM / 4), lane);

        // position i+2 into vA (overlaps vB's latency)
        if (i + 2 < PPW) {
            compute_idx(trow, sbase + i + 2, idx);
            issue_gathers(tables, idx, lane, vA);
        }
        // consume position i+1 (waits only on vB)
        if (i + 1 < PPW) {
            consume(vB, orow + (long)(i + 1) * (EDIM / 4), lane);
        }
    }
}

extern "C" void kernel_launch(void* const* d_in, const int* in_sizes, int n_in,
                              void* d_out, int out_size) {
    const int*   tokens = (const int*)d_in[0];
    const float* tables = (const float*)d_in[1];
    float*       out    = (float*)d_out;

    const int threads = 256;                       // 8 warps/block
    const int blocks  = NWARPS / (threads / 32);   // 2048 blocks
    ngram_embed_kernel<<<blocks, threads>>>(tokens, tables, out);
}